// round 2
// baseline (speedup 1.0000x reference)
#include <cuda_runtime.h>
#include <float.h>

// Fused: out[b,c,y,x] = relu( p1[b, c%128, y,x] + p2[b, c%64, y,x]
//                           + p3[b, c%32, y,x] + p4[b, c%16, y,x] + ff[b,c,y,x] )
// where pk = non-overlapping max-pool of input_tensor_k.
//
// One CTA per (b, y): computes all pooled values for this output row ONCE
// into SMEM (exactly-minimal HBM traffic), then assembles the 256-channel
// output row with float4 stores. 512 threads/CTA so the full grid (384 CTAs)
// is resident in one wave at ~65% occupancy for DRAM latency hiding.

#define NB 16
#define HW 24          // output spatial size
#define THREADS 512

__global__ __launch_bounds__(THREADS, 2)
void fused_ffblock_kernel(const float* __restrict__ t1,   // [16,128,48,48]
                          const float* __restrict__ t2,   // [16, 64,96,96]
                          const float* __restrict__ t3,   // [16, 32,192,192]
                          const float* __restrict__ t4,   // [16, 16,384,384]
                          const float* __restrict__ ff,   // [16,256,24,24]
                          float* __restrict__ out)        // [16,256,24,24]
{
    const int b = blockIdx.x / HW;
    const int y = blockIdx.x % HW;
    const int tid = threadIdx.x;

    __shared__ __align__(16) float p4s[16 * HW];
    __shared__ __align__(16) float p3s[32 * HW];
    __shared__ __align__(16) float p2s[64 * HW];
    __shared__ __align__(16) float p1s[128 * HW];

    // ---- t4: k=16, 16 channels, input 384x384. 384 items; 16 rows x 4 float4 each.
    for (int i = tid; i < 16 * HW; i += THREADS) {
        const int c = i / HW, x = i % HW;
        const float* rowp = t4 + ((c + b * 16) * 384 + y * 16) * 384 + x * 16;
        float4 m0 = make_float4(-FLT_MAX, -FLT_MAX, -FLT_MAX, -FLT_MAX);
        float4 m1 = m0, m2 = m0, m3 = m0;
        #pragma unroll 4
        for (int r = 0; r < 16; ++r) {
            const float4* p = reinterpret_cast<const float4*>(rowp + r * 384);
            float4 v0 = p[0], v1 = p[1], v2 = p[2], v3 = p[3];
            m0.x = fmaxf(m0.x, v0.x); m0.y = fmaxf(m0.y, v0.y);
            m0.z = fmaxf(m0.z, v0.z); m0.w = fmaxf(m0.w, v0.w);
            m1.x = fmaxf(m1.x, v1.x); m1.y = fmaxf(m1.y, v1.y);
            m1.z = fmaxf(m1.z, v1.z); m1.w = fmaxf(m1.w, v1.w);
            m2.x = fmaxf(m2.x, v2.x); m2.y = fmaxf(m2.y, v2.y);
            m2.z = fmaxf(m2.z, v2.z); m2.w = fmaxf(m2.w, v2.w);
            m3.x = fmaxf(m3.x, v3.x); m3.y = fmaxf(m3.y, v3.y);
            m3.z = fmaxf(m3.z, v3.z); m3.w = fmaxf(m3.w, v3.w);
        }
        float a = fmaxf(fmaxf(m0.x, m0.y), fmaxf(m0.z, m0.w));
        float bb = fmaxf(fmaxf(m1.x, m1.y), fmaxf(m1.z, m1.w));
        float cmx = fmaxf(fmaxf(m2.x, m2.y), fmaxf(m2.z, m2.w));
        float d = fmaxf(fmaxf(m3.x, m3.y), fmaxf(m3.z, m3.w));
        p4s[i] = fmaxf(fmaxf(a, bb), fmaxf(cmx, d));
    }

    // ---- t3: k=8, 32 channels, input 192x192. 768 items; 8 rows x 2 float4.
    for (int i = tid; i < 32 * HW; i += THREADS) {
        const int c = i / HW, x = i % HW;
        const float* rowp = t3 + ((c + b * 32) * 192 + y * 8) * 192 + x * 8;
        float4 m0 = make_float4(-FLT_MAX, -FLT_MAX, -FLT_MAX, -FLT_MAX);
        float4 m1 = m0;
        #pragma unroll
        for (int r = 0; r < 8; ++r) {
            const float4* p = reinterpret_cast<const float4*>(rowp + r * 192);
            float4 v0 = p[0], v1 = p[1];
            m0.x = fmaxf(m0.x, v0.x); m0.y = fmaxf(m0.y, v0.y);
            m0.z = fmaxf(m0.z, v0.z); m0.w = fmaxf(m0.w, v0.w);
            m1.x = fmaxf(m1.x, v1.x); m1.y = fmaxf(m1.y, v1.y);
            m1.z = fmaxf(m1.z, v1.z); m1.w = fmaxf(m1.w, v1.w);
        }
        float a = fmaxf(fmaxf(m0.x, m0.y), fmaxf(m0.z, m0.w));
        float bb = fmaxf(fmaxf(m1.x, m1.y), fmaxf(m1.z, m1.w));
        p3s[i] = fmaxf(a, bb);
    }

    // ---- t2: k=4, 64 channels, input 96x96. 1536 items; 4 rows x 1 float4.
    for (int i = tid; i < 64 * HW; i += THREADS) {
        const int c = i / HW, x = i % HW;
        const float* rowp = t2 + ((c + b * 64) * 96 + y * 4) * 96 + x * 4;
        float4 m0 = make_float4(-FLT_MAX, -FLT_MAX, -FLT_MAX, -FLT_MAX);
        #pragma unroll
        for (int r = 0; r < 4; ++r) {
            float4 v = *reinterpret_cast<const float4*>(rowp + r * 96);
            m0.x = fmaxf(m0.x, v.x); m0.y = fmaxf(m0.y, v.y);
            m0.z = fmaxf(m0.z, v.z); m0.w = fmaxf(m0.w, v.w);
        }
        p2s[i] = fmaxf(fmaxf(m0.x, m0.y), fmaxf(m0.z, m0.w));
    }

    // ---- t1: k=2, 128 channels, input 48x48. float4 path: each item covers
    // 2 adjacent output x's (one 4-wide window pair), 1536 items, 2 rows x float4.
    for (int i = tid; i < 128 * (HW / 2); i += THREADS) {
        const int c = i / (HW / 2), xp = i % (HW / 2);   // xp = x/2
        const float* rowp = t1 + ((c + b * 128) * 48 + y * 2) * 48 + xp * 4;
        float4 v0 = *reinterpret_cast<const float4*>(rowp);
        float4 v1 = *reinterpret_cast<const float4*>(rowp + 48);
        p1s[c * HW + xp * 2 + 0] = fmaxf(fmaxf(v0.x, v0.y), fmaxf(v1.x, v1.y));
        p1s[c * HW + xp * 2 + 1] = fmaxf(fmaxf(v0.z, v0.w), fmaxf(v1.z, v1.w));
    }

    __syncthreads();

    // ---- assemble output row: 256 channels x 24 x, as 256 x 6 float4 items.
    const int out_row_base = ((b * 256) * HW + y) * HW;  // + c*HW*HW + x
    for (int j = tid; j < 256 * (HW / 4); j += THREADS) {
        const int c  = j / (HW / 4);
        const int x0 = (j % (HW / 4)) * 4;
        const int c1 = c & 127, c2 = c & 63, c3 = c & 31, c4 = c & 15;

        float4 f = *reinterpret_cast<const float4*>(ff + out_row_base + c * (HW * HW) + x0);
        float4 a1 = *reinterpret_cast<const float4*>(&p1s[c1 * HW + x0]);
        float4 a2 = *reinterpret_cast<const float4*>(&p2s[c2 * HW + x0]);
        float4 a3 = *reinterpret_cast<const float4*>(&p3s[c3 * HW + x0]);
        float4 a4 = *reinterpret_cast<const float4*>(&p4s[c4 * HW + x0]);

        float4 r;
        r.x = fmaxf(f.x + a1.x + a2.x + a3.x + a4.x, 0.f);
        r.y = fmaxf(f.y + a1.y + a2.y + a3.y + a4.y, 0.f);
        r.z = fmaxf(f.z + a1.z + a2.z + a3.z + a4.z, 0.f);
        r.w = fmaxf(f.w + a1.w + a2.w + a3.w + a4.w, 0.f);

        *reinterpret_cast<float4*>(out + out_row_base + c * (HW * HW) + x0) = r;
    }
}

extern "C" void kernel_launch(void* const* d_in, const int* in_sizes, int n_in,
                              void* d_out, int out_size) {
    const float* t1 = (const float*)d_in[0];
    const float* t2 = (const float*)d_in[1];
    const float* t3 = (const float*)d_in[2];
    const float* t4 = (const float*)d_in[3];
    const float* ff = (const float*)d_in[4];
    float* out = (float*)d_out;

    dim3 grid(NB * HW);   // 384 CTAs: one per (batch, output row)
    dim3 block(THREADS);
    fused_ffblock_kernel<<<grid, block>>>(t1, t2, t3, t4, ff, out);
}

// round 3
// speedup vs baseline: 1.2142x; 1.2142x over previous
#include <cuda_runtime.h>
#include <float.h>

// Fused: out[b,c,y,x] = relu( p1[b, c%128, y,x] + p2[b, c%64, y,x]
//                           + p3[b, c%32, y,x] + p4[b, c%16, y,x] + ff[b,c,y,x] )
// where pk = non-overlapping max-pool of input_tensor_k.
//
// One CTA per (b, y, x-half): computes all pooled values for its half-row ONCE
// into SMEM (minimal HBM traffic; x-split partitions input reads exactly),
// then assembles the 256-channel half-row with float4 stores.
// 768 CTAs x 256 threads, 6 CTAs/SM -> single wave at ~65% occupancy.

#define NB 16
#define HW 24          // output spatial size
#define HX 12          // x extent per CTA (half row)
#define THREADS 256

__global__ __launch_bounds__(THREADS, 6)
void fused_ffblock_kernel(const float* __restrict__ t1,   // [16,128,48,48]
                          const float* __restrict__ t2,   // [16, 64,96,96]
                          const float* __restrict__ t3,   // [16, 32,192,192]
                          const float* __restrict__ t4,   // [16, 16,384,384]
                          const float* __restrict__ ff,   // [16,256,24,24]
                          float* __restrict__ out)        // [16,256,24,24]
{
    const int xh  = blockIdx.x & 1;          // x-half: 0 -> [0,12), 1 -> [12,24)
    const int y   = (blockIdx.x >> 1) % HW;
    const int b   = (blockIdx.x >> 1) / HW;
    const int tid = threadIdx.x;
    const int xbase = xh * HX;

    __shared__ __align__(16) float p4s[16 * HX];
    __shared__ __align__(16) float p3s[32 * HX];
    __shared__ __align__(16) float p2s[64 * HX];
    __shared__ __align__(16) float p1s[128 * HX];

    // ---- t4: k=16, 16 channels, input 384x384. 192 items; 16 rows x 4 float4.
    for (int i = tid; i < 16 * HX; i += THREADS) {
        const int c = i / HX, l = i % HX;
        const float* rowp = t4 + ((c + b * 16) * 384 + y * 16) * 384 + (xbase + l) * 16;
        float4 m = make_float4(-FLT_MAX, -FLT_MAX, -FLT_MAX, -FLT_MAX);
        #pragma unroll 4
        for (int r = 0; r < 16; ++r) {
            const float4* p = reinterpret_cast<const float4*>(rowp + r * 384);
            float4 v0 = p[0], v1 = p[1], v2 = p[2], v3 = p[3];
            float4 w;
            w.x = fmaxf(fmaxf(v0.x, v1.x), fmaxf(v2.x, v3.x));
            w.y = fmaxf(fmaxf(v0.y, v1.y), fmaxf(v2.y, v3.y));
            w.z = fmaxf(fmaxf(v0.z, v1.z), fmaxf(v2.z, v3.z));
            w.w = fmaxf(fmaxf(v0.w, v1.w), fmaxf(v2.w, v3.w));
            m.x = fmaxf(m.x, w.x); m.y = fmaxf(m.y, w.y);
            m.z = fmaxf(m.z, w.z); m.w = fmaxf(m.w, w.w);
        }
        p4s[i] = fmaxf(fmaxf(m.x, m.y), fmaxf(m.z, m.w));
    }

    // ---- t3: k=8, 32 channels, input 192x192. 384 items; 8 rows x 2 float4.
    for (int i = tid; i < 32 * HX; i += THREADS) {
        const int c = i / HX, l = i % HX;
        const float* rowp = t3 + ((c + b * 32) * 192 + y * 8) * 192 + (xbase + l) * 8;
        float4 m = make_float4(-FLT_MAX, -FLT_MAX, -FLT_MAX, -FLT_MAX);
        #pragma unroll
        for (int r = 0; r < 8; ++r) {
            const float4* p = reinterpret_cast<const float4*>(rowp + r * 192);
            float4 v0 = p[0], v1 = p[1];
            m.x = fmaxf(m.x, fmaxf(v0.x, v1.x));
            m.y = fmaxf(m.y, fmaxf(v0.y, v1.y));
            m.z = fmaxf(m.z, fmaxf(v0.z, v1.z));
            m.w = fmaxf(m.w, fmaxf(v0.w, v1.w));
        }
        p3s[i] = fmaxf(fmaxf(m.x, m.y), fmaxf(m.z, m.w));
    }

    // ---- t2: k=4, 64 channels, input 96x96. 768 items; 4 rows x 1 float4.
    for (int i = tid; i < 64 * HX; i += THREADS) {
        const int c = i / HX, l = i % HX;
        const float* rowp = t2 + ((c + b * 64) * 96 + y * 4) * 96 + (xbase + l) * 4;
        float4 m = make_float4(-FLT_MAX, -FLT_MAX, -FLT_MAX, -FLT_MAX);
        #pragma unroll
        for (int r = 0; r < 4; ++r) {
            float4 v = *reinterpret_cast<const float4*>(rowp + r * 96);
            m.x = fmaxf(m.x, v.x); m.y = fmaxf(m.y, v.y);
            m.z = fmaxf(m.z, v.z); m.w = fmaxf(m.w, v.w);
        }
        p2s[i] = fmaxf(fmaxf(m.x, m.y), fmaxf(m.z, m.w));
    }

    // ---- t1: k=2, 128 channels, input 48x48. Each item = 2 adjacent outputs
    // via float4: 128 * 6 = 768 items; 2 rows x 1 float4.
    for (int i = tid; i < 128 * (HX / 2); i += THREADS) {
        const int c = i / (HX / 2), xp = i % (HX / 2);   // xp = local x / 2
        const float* rowp = t1 + ((c + b * 128) * 48 + y * 2) * 48 + xbase * 2 + xp * 4;
        float4 v0 = *reinterpret_cast<const float4*>(rowp);
        float4 v1 = *reinterpret_cast<const float4*>(rowp + 48);
        p1s[c * HX + xp * 2 + 0] = fmaxf(fmaxf(v0.x, v0.y), fmaxf(v1.x, v1.y));
        p1s[c * HX + xp * 2 + 1] = fmaxf(fmaxf(v0.z, v0.w), fmaxf(v1.z, v1.w));
    }

    __syncthreads();

    // ---- assemble: 256 channels x 12 x, as 256 x 3 float4 items = 768.
    const int row_base = ((b * 256) * HW + y) * HW + xbase;  // + c*HW*HW + local x
    for (int j = tid; j < 256 * (HX / 4); j += THREADS) {
        const int c  = j / (HX / 4);
        const int x0 = (j % (HX / 4)) * 4;                  // local x
        const int c1 = c & 127, c2 = c & 63, c3 = c & 31, c4 = c & 15;
        const int g  = row_base + c * (HW * HW) + x0;

        float4 f  = *reinterpret_cast<const float4*>(ff + g);
        float4 a1 = *reinterpret_cast<const float4*>(&p1s[c1 * HX + x0]);
        float4 a2 = *reinterpret_cast<const float4*>(&p2s[c2 * HX + x0]);
        float4 a3 = *reinterpret_cast<const float4*>(&p3s[c3 * HX + x0]);
        float4 a4 = *reinterpret_cast<const float4*>(&p4s[c4 * HX + x0]);

        float4 r;
        r.x = fmaxf(f.x + a1.x + a2.x + a3.x + a4.x, 0.f);
        r.y = fmaxf(f.y + a1.y + a2.y + a3.y + a4.y, 0.f);
        r.z = fmaxf(f.z + a1.z + a2.z + a3.z + a4.z, 0.f);
        r.w = fmaxf(f.w + a1.w + a2.w + a3.w + a4.w, 0.f);

        *reinterpret_cast<float4*>(out + g) = r;
    }
}

extern "C" void kernel_launch(void* const* d_in, const int* in_sizes, int n_in,
                              void* d_out, int out_size) {
    const float* t1 = (const float*)d_in[0];
    const float* t2 = (const float*)d_in[1];
    const float* t3 = (const float*)d_in[2];
    const float* t4 = (const float*)d_in[3];
    const float* ff = (const float*)d_in[4];
    float* out = (float*)d_out;

    dim3 grid(NB * HW * 2);   // 768 CTAs: one per (batch, row, x-half)
    dim3 block(THREADS);
    fused_ffblock_kernel<<<grid, block>>>(t1, t2, t3, t4, ff, out);
}